// round 2
// baseline (speedup 1.0000x reference)
#include <cuda_runtime.h>
#include <cuda_bf16.h>
#include <math.h>

// ---------------- problem constants ----------------
#define EMB    300
#define SEQ    100
#define KW     5
#define KN     50
#define KMAX   3
#define MLP1   75
#define LP     (SEQ - KW + 1)   // 96
#define EPAD   301              // smem E row pad (conflict-free for 4-row strided reads)
#define WSTRIDE 10              // per-n stride (floats): 5 w * 2 (duplicated pair)
#define EC     30               // e-chunk staged in smem
#define NCHUNK (EMB / EC)       // 10

// ---------------- device scratch (no allocations allowed) ----------------
__device__ float g_cv[EMB];
__device__ float g_gate[KN];
__device__ float g_bias[KN];
__device__ float g_wdup[EMB * KN * WSTRIDE];   // [e][n][w][2], value duplicated

// packed fp32 FMA (sm_103a): d = a*b + c elementwise on 2 lanes
__device__ __forceinline__ float2 ffma2(float2 a, float2 b, float2 c) {
    float2 d;
    asm("fma.rn.f32x2 %0, %1, %2, %3;"
        : "=l"(*reinterpret_cast<unsigned long long*>(&d))
        : "l"(*reinterpret_cast<unsigned long long*>(&a)),
          "l"(*reinterpret_cast<unsigned long long*>(&b)),
          "l"(*reinterpret_cast<unsigned long long*>(&c)));
    return d;
}

// ---------------- prep kernel 1: class vec, gate, folded bias (parallel) ----
__global__ void dazer_prep1(const int* __restrict__ q,
                            const float* __restrict__ emb,
                            const float* __restrict__ gate_w,
                            const float* __restrict__ gate_b,
                            const float* __restrict__ conv_w,
                            const float* __restrict__ conv_b) {
    __shared__ float cvs[EMB];
    const int t = threadIdx.x;            // 512 threads
    if (t < EMB) {
        float s = 0.f;
        #pragma unroll
        for (int k = 0; k < 5; k++) s += emb[(size_t)q[k] * EMB + t];
        s *= 0.2f;
        cvs[t] = s;
        g_cv[t] = s;
    }
    __syncthreads();

    const int warp = t >> 5, lane = t & 31;

    // gate: one warp per filter n
    for (int n = warp; n < KN; n += 16) {
        float s = 0.f;
        for (int e = lane; e < EMB; e += 32) s += cvs[e] * gate_w[e * KN + n];
        #pragma unroll
        for (int o = 16; o; o >>= 1) s += __shfl_down_sync(0xffffffffu, s, o);
        if (lane == 0) g_gate[n] = 1.f / (1.f + expf(-(s + gate_b[n])));
    }

    // folded bias: bias[n] = conv_b[n] + sum_{w,e} cv[e] * W3[w,e,n]
    for (int n = warp; n < KN; n += 16) {
        float s = 0.f;
        for (int idx = lane; idx < KW * EMB; idx += 32) {
            int w = idx / EMB, e = idx - w * EMB;
            s += cvs[e] * conv_w[(w * (3 * EMB) + 2 * EMB + e) * KN + n];
        }
        #pragma unroll
        for (int o = 16; o; o >>= 1) s += __shfl_down_sync(0xffffffffu, s, o);
        if (lane == 0) g_bias[n] = s + conv_b[n];
    }
}

// ---------------- prep kernel 2: folded + DUPLICATED conv weights -----------
// Weff[w,e,n] = W1 + cv[e]*W2 - W3 ; stored twice at g_wdup[(e*KN+n)*10 + w*2 + {0,1}]
__global__ void dazer_prep2(const float* __restrict__ conv_w) {
    const int total = EMB * KN * KW;   // 75000
    for (int idx = blockIdx.x * blockDim.x + threadIdx.x; idx < total;
         idx += gridDim.x * blockDim.x) {
        int w    = idx % KW;
        int rest = idx / KW;            // e*KN + n
        int n    = rest % KN;
        int e    = rest / KN;
        int base = w * (3 * EMB);
        float v = conv_w[(base + e) * KN + n]
                + g_cv[e] * conv_w[(base + EMB + e) * KN + n]
                -            conv_w[(base + 2 * EMB + e) * KN + n];
        int o = (e * KN + n) * WSTRIDE + w * 2;
        g_wdup[o]     = v;
        g_wdup[o + 1] = v;
    }
}

// ---------------- main fused kernel: one document per CTA ----------------
// smem floats: E 100*301 | Ws 30*50*10 | convs 96*50 | enc 152 | mlp1 76 | docids 100
#define SMEM_FLOATS (SEQ * EPAD + EC * KN * WSTRIDE + LP * KN + 152 + 76 + 100)

__global__ __launch_bounds__(256, 1)
void dazer_main(const int* __restrict__ input_d,
                const float* __restrict__ emb,
                const float* __restrict__ hid_w,
                const float* __restrict__ hid_b,
                const float* __restrict__ score_w,
                const float* __restrict__ score_b,
                float* __restrict__ out, int Btot) {
    extern __shared__ float sm[];
    float* E      = sm;                         // [100][301]
    float* Ws     = E + SEQ * EPAD;             // [30][50][10]  (16B aligned: 120400%16==0)
    float* convs  = Ws + EC * KN * WSTRIDE;     // [96][50]
    float* enc    = convs + LP * KN;            // [152]
    float* mlp1s  = enc + 152;                  // [76]
    int*   docids = (int*)(mlp1s + 76);         // [100]

    const int tid = threadIdx.x;
    const int b   = blockIdx.x;

    if (tid < SEQ) docids[tid] = input_d[b * SEQ + tid];
    __syncthreads();

    // gather embeddings (coalesced LDG, conflict-free STS into padded rows)
    for (int idx = tid; idx < SEQ * EMB; idx += blockDim.x) {
        int s = idx / EMB;
        int e = idx - s * EMB;
        E[s * EPAD + e] = emb[(size_t)docids[s] * EMB + e];
    }

    // thread tile: TT=4 conv rows x TN=5 filters, 240 active threads
    const int  tg     = tid / 10;          // 0..23
    const int  ng     = tid - tg * 10;     // 0..9
    const int  t0     = tg * 4;            // 0..92
    const int  n0     = ng * 5;            // 0..45
    const bool active = (tid < 240);

    float2 a01[5], a23[5];
    #pragma unroll
    for (int j = 0; j < 5; j++) { a01[j] = make_float2(0.f, 0.f); a23[j] = make_float2(0.f, 0.f); }

    for (int c = 0; c < NCHUNK; c++) {
        // stage duplicated weight chunk (float4 copy, identical layout)
        {
            const float4* src = (const float4*)(g_wdup + c * EC * KN * WSTRIDE);
            float4* dst = (float4*)Ws;
            #pragma unroll 4
            for (int i = tid; i < EC * KN * WSTRIDE / 4; i += 256) dst[i] = src[i];
        }
        __syncthreads();

        if (active) {
            #pragma unroll 2
            for (int e = 0; e < EC; e++) {
                const int ee = c * EC + e;
                // sliding-window pairs (t, t+1) loaded straight into float2 halves
                float2 pr[7];
                #pragma unroll
                for (int i = 0; i < 7; i++) {
                    pr[i].x = E[(t0 + i) * EPAD + ee];
                    pr[i].y = E[(t0 + i + 1) * EPAD + ee];
                }
                const float* wb = Ws + e * (KN * WSTRIDE) + n0 * WSTRIDE;
                #pragma unroll
                for (int j = 0; j < 5; j++) {
                    const float2* wp = (const float2*)(wb + j * WSTRIDE);
                    #pragma unroll
                    for (int w = 0; w < 5; w++) {
                        float2 wv = wp[w];              // LDS.64 -> (v, v), no MOVs
                        a01[j] = ffma2(pr[w],     wv, a01[j]);
                        a23[j] = ffma2(pr[w + 2], wv, a23[j]);
                    }
                }
            }
        }
        __syncthreads();
    }

    // gate + bias, write conv outputs to smem
    if (active) {
        #pragma unroll
        for (int j = 0; j < 5; j++) {
            int n = n0 + j;
            float gg = g_gate[n], bb = g_bias[n];
            convs[(t0 + 0) * KN + n] = gg * (a01[j].x + bb);
            convs[(t0 + 1) * KN + n] = gg * (a01[j].y + bb);
            convs[(t0 + 2) * KN + n] = gg * (a23[j].x + bb);
            convs[(t0 + 3) * KN + n] = gg * (a23[j].y + bb);
        }
    }
    __syncthreads();

    // top-3 (kmax) per filter, original-order output (strict > == jax top_k tie-break)
    if (tid < KN) {
        const int n = tid;
        float v1 = -1e30f, v2 = -1e30f, v3 = -1e30f;
        int   i1 = 0, i2 = 0, i3 = 0;
        for (int t = 0; t < LP; t++) {
            float v = convs[t * KN + n];
            if (v > v1)      { v3 = v2; i3 = i2; v2 = v1; i2 = i1; v1 = v; i1 = t; }
            else if (v > v2) { v3 = v2; i3 = i2; v2 = v;  i2 = t; }
            else if (v > v3) { v3 = v;  i3 = t; }
        }
        float va = v1, vb = v2, vc = v3; int ia = i1, ib = i2, ic = i3;
        if (ia > ib) { float tv = va; va = vb; vb = tv; int ti = ia; ia = ib; ib = ti; }
        if (ib > ic) { float tv = vb; vb = vc; vc = tv; int ti = ib; ib = ic; ic = ti; }
        if (ia > ib) { float tv = va; va = vb; vb = tv; int ti = ia; ia = ib; ib = ti; }
        enc[n * 3 + 0] = va;
        enc[n * 3 + 1] = vb;
        enc[n * 3 + 2] = vc;
    }
    __syncthreads();

    // mlp1 = tanh(enc @ hid_w + hid_b)
    if (tid < MLP1) {
        float s = hid_b[tid];
        #pragma unroll 5
        for (int i = 0; i < KN * KMAX; i++) s += enc[i] * hid_w[i * MLP1 + tid];
        float m = tanhf(s);
        mlp1s[tid] = m;
        out[(size_t)b * MLP1 + tid] = m;
    }
    __syncthreads();

    // score = tanh(mlp1 @ score_w + score_b)
    if (tid == 0) {
        float s = score_b[0];
        for (int j = 0; j < MLP1; j++) s += mlp1s[j] * score_w[j];
        out[(size_t)Btot * MLP1 + b] = tanhf(s);
    }
}

// ---------------- launch ----------------
extern "C" void kernel_launch(void* const* d_in, const int* in_sizes, int n_in,
                              void* d_out, int out_size) {
    const int*   input_q   = (const int*)  d_in[0];
    const int*   input_d   = (const int*)  d_in[1];
    const float* emb_table = (const float*)d_in[2];
    const float* conv_w    = (const float*)d_in[3];
    const float* conv_b    = (const float*)d_in[4];
    const float* gate_w    = (const float*)d_in[5];
    const float* gate_b    = (const float*)d_in[6];
    const float* hid_w     = (const float*)d_in[7];
    const float* hid_b     = (const float*)d_in[8];
    const float* score_w   = (const float*)d_in[9];
    const float* score_b   = (const float*)d_in[10];
    float* out = (float*)d_out;

    const int Btot = in_sizes[1] / SEQ;   // 2048
    const int smem_bytes = SMEM_FLOATS * (int)sizeof(float);

    cudaFuncSetAttribute(dazer_main, cudaFuncAttributeMaxDynamicSharedMemorySize, smem_bytes);

    dazer_prep1<<<1, 512>>>(input_q, emb_table, gate_w, gate_b, conv_w, conv_b);
    dazer_prep2<<<160, 256>>>(conv_w);
    dazer_main<<<Btot, 256, smem_bytes>>>(input_d, emb_table, hid_w, hid_b,
                                          score_w, score_b, out, Btot);
}

// round 4
// speedup vs baseline: 1.0098x; 1.0098x over previous
#include <cuda_runtime.h>
#include <cuda_bf16.h>
#include <math.h>

// ---------------- problem constants ----------------
#define EMB    300
#define SEQ    100
#define KW     5
#define KN     50
#define KMAX   3
#define MLP1   75
#define LP     (SEQ - KW + 1)   // 96
#define EPAD   308              // smem E row pad: %4==0 (LDS.128)
#define NQ     (EMB / 4)        // 75 e-quads

// ---------------- device scratch ----------------
__device__ float g_cv[EMB];
__device__ float g_gate[KN];
__device__ float g_bias[KN];
__device__ __align__(16) float g_w2[KN * KW * EMB];   // [n][w][e], e contiguous

// packed fp32 FMA (sm_103a): d = a*b + c elementwise on 2 lanes
__device__ __forceinline__ float2 ffma2(float2 a, float2 b, float2 c) {
    float2 d;
    asm("fma.rn.f32x2 %0, %1, %2, %3;"
        : "=l"(*reinterpret_cast<unsigned long long*>(&d))
        : "l"(*reinterpret_cast<unsigned long long*>(&a)),
          "l"(*reinterpret_cast<unsigned long long*>(&b)),
          "l"(*reinterpret_cast<unsigned long long*>(&c)));
    return d;
}

// ---------------- prepA: class vector ----------------
__global__ void dazer_prepA(const int* __restrict__ q,
                            const float* __restrict__ emb) {
    int t = threadIdx.x;
    if (t < EMB) {
        float s = 0.f;
        #pragma unroll
        for (int k = 0; k < 5; k++) s += emb[(size_t)q[k] * EMB + t];
        g_cv[t] = s * 0.2f;
    }
}

// ---------------- prepB: gate + folded bias (blocks 0..49) and W fold (blocks 50..149)
__global__ void dazer_prepB(const float* __restrict__ conv_w,
                            const float* __restrict__ conv_b,
                            const float* __restrict__ gate_w,
                            const float* __restrict__ gate_b) {
    __shared__ float red[256];
    __shared__ float cvs[EMB];
    const int tid = threadIdx.x;
    const int bid = blockIdx.x;

    // FIX(R3 bug): blockDim=256 < EMB=300 — must stride, not mask
    for (int e = tid; e < EMB; e += 256) cvs[e] = g_cv[e];
    __syncthreads();

    if (bid < KN) {
        const int n = bid;
        // gate
        float s = 0.f;
        for (int e = tid; e < EMB; e += 256) s += cvs[e] * gate_w[e * KN + n];
        red[tid] = s; __syncthreads();
        for (int o = 128; o; o >>= 1) { if (tid < o) red[tid] += red[tid + o]; __syncthreads(); }
        if (tid == 0) g_gate[n] = 1.f / (1.f + expf(-(red[0] + gate_b[n])));
        __syncthreads();
        // folded bias: conv_b[n] + sum_{w,e} cv[e]*W3[w,e,n]
        float bs = 0.f;
        for (int idx = tid; idx < KW * EMB; idx += 256) {
            int w = idx / EMB, e = idx - w * EMB;
            bs += cvs[e] * conv_w[(w * (3 * EMB) + 2 * EMB + e) * KN + n];
        }
        red[tid] = bs; __syncthreads();
        for (int o = 128; o; o >>= 1) { if (tid < o) red[tid] += red[tid + o]; __syncthreads(); }
        if (tid == 0) g_bias[n] = red[0] + conv_b[n];
    } else {
        // fold: g_w2[(n*5+w)*300 + e] = W1 + cv[e]*W2 - W3
        const int total = KN * KW * EMB;   // 75000
        for (int idx = (bid - KN) * 256 + tid; idx < total; idx += 100 * 256) {
            int e    = idx % EMB;
            int rest = idx / EMB;      // n*5 + w
            int w    = rest % KW;
            int n    = rest / KW;
            int base = w * (3 * EMB);
            g_w2[idx] = conv_w[(base + e) * KN + n]
                      + cvs[e] * conv_w[(base + EMB + e) * KN + n]
                      -          conv_w[(base + 2 * EMB + e) * KN + n];
        }
    }
}

// ---------------- main fused kernel: one document per CTA ----------------
// smem floats: E 100*308 | convs 96*50 | enc 152 | mlp1 76 | docids 100
#define SMEM_FLOATS (SEQ * EPAD + LP * KN + 152 + 76 + 100)

__global__ __launch_bounds__(256, 1)
void dazer_main(const int* __restrict__ input_d,
                const float* __restrict__ emb,
                const float* __restrict__ hid_w,
                const float* __restrict__ hid_b,
                const float* __restrict__ score_w,
                const float* __restrict__ score_b,
                float* __restrict__ out, int Btot) {
    extern __shared__ float sm[];
    float* E      = sm;                         // [100][308]
    float* convs  = E + SEQ * EPAD;             // [96][50]
    float* enc    = convs + LP * KN;            // [152]
    float* mlp1s  = enc + 152;                  // [76]
    int*   docids = (int*)(mlp1s + 76);         // [100]

    const int tid = threadIdx.x;
    const int b   = blockIdx.x;

    if (tid < SEQ) docids[tid] = input_d[b * SEQ + tid];
    __syncthreads();

    // gather embeddings (coalesced LDG -> padded smem rows)
    for (int idx = tid; idx < SEQ * EMB; idx += 256) {
        int s = idx / EMB;
        int e = idx - s * EMB;
        E[s * EPAD + e] = emb[(size_t)docids[s] * EMB + e];
    }
    __syncthreads();

    // thread tile: 4 t-rows x 5 filters. 240 real tiles; threads 240..255
    // recompute tile (23,9) as harmless dummies so ALL threads hit barriers.
    int tg = tid / 10;          // 0..25
    int ng = tid - tg * 10;     // 0..9
    const bool real = (tid < 240);
    if (!real) { tg = 23; ng = 9; }
    const int t0 = tg * 4;
    const int n0 = ng * 5;

    float2 acc[4][5];
    #pragma unroll
    for (int k = 0; k < 4; k++)
        #pragma unroll
        for (int j = 0; j < 5; j++) acc[k][j] = make_float2(0.f, 0.f);

    const float4* __restrict__ Wq = (const float4*)g_w2;  // [(n*5+w)*75 + eq]

    #pragma unroll 1
    for (int eq = 0; eq < NQ; eq++) {
        // E rows t0..t0+7, this e-quad (LDS.128 each)
        float4 E4[8];
        #pragma unroll
        for (int k = 0; k < 8; k++)
            E4[k] = *(const float4*)&E[(t0 + k) * EPAD + eq * 4];

        #pragma unroll
        for (int j = 0; j < 5; j++) {
            #pragma unroll
            for (int w = 0; w < 5; w++) {
                float4 w4 = Wq[((n0 + j) * KW + w) * NQ + eq];   // LDG.128 (L1/L2)
                float2 wlo = make_float2(w4.x, w4.y);
                float2 whi = make_float2(w4.z, w4.w);
                #pragma unroll
                for (int k = 0; k < 4; k++) {
                    float2 elo = make_float2(E4[w + k].x, E4[w + k].y);
                    float2 ehi = make_float2(E4[w + k].z, E4[w + k].w);
                    acc[k][j] = ffma2(elo, wlo, acc[k][j]);
                    acc[k][j] = ffma2(ehi, whi, acc[k][j]);
                }
            }
        }
        // keep warps in lockstep so W lines hit L1 across warps
        if ((eq % 15) == 14) __syncthreads();
    }

    // gate + bias, write conv outputs to smem
    if (real) {
        #pragma unroll
        for (int j = 0; j < 5; j++) {
            int n = n0 + j;
            float gg = g_gate[n], bb = g_bias[n];
            #pragma unroll
            for (int k = 0; k < 4; k++)
                convs[(t0 + k) * KN + n] = gg * ((acc[k][j].x + acc[k][j].y) + bb);
        }
    }
    __syncthreads();

    // top-3 (kmax) per filter, original-order (strict > == jax top_k tie-break)
    if (tid < KN) {
        const int n = tid;
        float v1 = -1e30f, v2 = -1e30f, v3 = -1e30f;
        int   i1 = 0, i2 = 0, i3 = 0;
        for (int t = 0; t < LP; t++) {
            float v = convs[t * KN + n];
            if (v > v1)      { v3 = v2; i3 = i2; v2 = v1; i2 = i1; v1 = v; i1 = t; }
            else if (v > v2) { v3 = v2; i3 = i2; v2 = v;  i2 = t; }
            else if (v > v3) { v3 = v;  i3 = t; }
        }
        float va = v1, vb = v2, vc = v3; int ia = i1, ib = i2, ic = i3;
        if (ia > ib) { float tv = va; va = vb; vb = tv; int ti = ia; ia = ib; ib = ti; }
        if (ib > ic) { float tv = vb; vb = vc; vc = tv; int ti = ib; ib = ic; ic = ti; }
        if (ia > ib) { float tv = va; va = vb; vb = tv; int ti = ia; ia = ib; ib = ti; }
        enc[n * 3 + 0] = va;
        enc[n * 3 + 1] = vb;
        enc[n * 3 + 2] = vc;
    }
    __syncthreads();

    // mlp1 = tanh(enc @ hid_w + hid_b)
    if (tid < MLP1) {
        float s = hid_b[tid];
        #pragma unroll 5
        for (int i = 0; i < KN * KMAX; i++) s += enc[i] * hid_w[i * MLP1 + tid];
        float m = tanhf(s);
        mlp1s[tid] = m;
        out[(size_t)b * MLP1 + tid] = m;
    }
    __syncthreads();

    // score = tanh(mlp1 @ score_w + score_b)
    if (tid == 0) {
        float s = score_b[0];
        for (int j = 0; j < MLP1; j++) s += mlp1s[j] * score_w[j];
        out[(size_t)Btot * MLP1 + b] = tanhf(s);
    }
}

// ---------------- launch ----------------
extern "C" void kernel_launch(void* const* d_in, const int* in_sizes, int n_in,
                              void* d_out, int out_size) {
    const int*   input_q   = (const int*)  d_in[0];
    const int*   input_d   = (const int*)  d_in[1];
    const float* emb_table = (const float*)d_in[2];
    const float* conv_w    = (const float*)d_in[3];
    const float* conv_b    = (const float*)d_in[4];
    const float* gate_w    = (const float*)d_in[5];
    const float* gate_b    = (const float*)d_in[6];
    const float* hid_w     = (const float*)d_in[7];
    const float* hid_b     = (const float*)d_in[8];
    const float* score_w   = (const float*)d_in[9];
    const float* score_b   = (const float*)d_in[10];
    float* out = (float*)d_out;

    const int Btot = in_sizes[1] / SEQ;   // 2048
    const int smem_bytes = SMEM_FLOATS * (int)sizeof(float);

    cudaFuncSetAttribute(dazer_main, cudaFuncAttributeMaxDynamicSharedMemorySize, smem_bytes);

    dazer_prepA<<<1, 320>>>(input_q, emb_table);
    dazer_prepB<<<150, 256>>>(conv_w, conv_b, gate_w, gate_b);
    dazer_main<<<Btot, 256, smem_bytes>>>(input_d, emb_table, hid_w, hid_b,
                                          score_w, score_b, out, Btot);
}

// round 5
// speedup vs baseline: 1.2584x; 1.2462x over previous
#include <cuda_runtime.h>
#include <cuda_bf16.h>
#include <math.h>

// ---------------- problem constants ----------------
#define EMB    300
#define SEQ    100
#define KW     5
#define KN     50
#define KMAX   3
#define MLP1   75
#define LP     (SEQ - KW + 1)   // 96
#define EPAD   308              // smem E row pad: %4==0 (LDS.128)
#define NQ     (EMB / 4)        // 75 e-quads
#define CE     60               // e per staged chunk (15 e-quads)
#define CQ     (CE / 4)         // 15 e-quads per chunk
#define NCH    (EMB / CE)       // 5 chunks
#define CHFLT  (KN * KW * CE)   // 15000 floats per chunk (60 KB)

// ---------------- device scratch ----------------
__device__ float g_cv[EMB];
__device__ float g_gate[KN];
__device__ float g_bias[KN];
// chunked layout: g_w2[c*CHFLT + (n*KW+w)*CE + ei], e = c*CE + ei
__device__ __align__(16) float g_w2[KN * KW * EMB];

// packed fp32 FMA (sm_103a): d = a*b + c elementwise on 2 lanes
__device__ __forceinline__ float2 ffma2(float2 a, float2 b, float2 c) {
    float2 d;
    asm("fma.rn.f32x2 %0, %1, %2, %3;"
        : "=l"(*reinterpret_cast<unsigned long long*>(&d))
        : "l"(*reinterpret_cast<unsigned long long*>(&a)),
          "l"(*reinterpret_cast<unsigned long long*>(&b)),
          "l"(*reinterpret_cast<unsigned long long*>(&c)));
    return d;
}

// ---------------- prepA: class vector ----------------
__global__ void dazer_prepA(const int* __restrict__ q,
                            const float* __restrict__ emb) {
    int t = threadIdx.x;
    if (t < EMB) {
        float s = 0.f;
        #pragma unroll
        for (int k = 0; k < 5; k++) s += emb[(size_t)q[k] * EMB + t];
        g_cv[t] = s * 0.2f;
    }
}

// ---------------- prepB: gate + folded bias (blocks 0..49) and W fold (blocks 50..149)
__global__ void dazer_prepB(const float* __restrict__ conv_w,
                            const float* __restrict__ conv_b,
                            const float* __restrict__ gate_w,
                            const float* __restrict__ gate_b) {
    __shared__ float red[256];
    __shared__ float cvs[EMB];
    const int tid = threadIdx.x;
    const int bid = blockIdx.x;

    for (int e = tid; e < EMB; e += 256) cvs[e] = g_cv[e];
    __syncthreads();

    if (bid < KN) {
        const int n = bid;
        // gate
        float s = 0.f;
        for (int e = tid; e < EMB; e += 256) s += cvs[e] * gate_w[e * KN + n];
        red[tid] = s; __syncthreads();
        for (int o = 128; o; o >>= 1) { if (tid < o) red[tid] += red[tid + o]; __syncthreads(); }
        if (tid == 0) g_gate[n] = 1.f / (1.f + expf(-(red[0] + gate_b[n])));
        __syncthreads();
        // folded bias: conv_b[n] + sum_{w,e} cv[e]*W3[w,e,n]
        float bs = 0.f;
        for (int idx = tid; idx < KW * EMB; idx += 256) {
            int w = idx / EMB, e = idx - w * EMB;
            bs += cvs[e] * conv_w[(w * (3 * EMB) + 2 * EMB + e) * KN + n];
        }
        red[tid] = bs; __syncthreads();
        for (int o = 128; o; o >>= 1) { if (tid < o) red[tid] += red[tid + o]; __syncthreads(); }
        if (tid == 0) g_bias[n] = red[0] + conv_b[n];
    } else {
        // fold into CHUNKED layout: g_w2[c*CHFLT + (n*5+w)*CE + ei] = W1 + cv[e]*W2 - W3
        const int total = KN * KW * EMB;   // 75000
        for (int idx = (bid - KN) * 256 + tid; idx < total; idx += 100 * 256) {
            int c    = idx / CHFLT;
            int r    = idx - c * CHFLT;
            int nw   = r / CE;          // n*5 + w
            int ei   = r - nw * CE;
            int w    = nw % KW;
            int n    = nw / KW;
            int e    = c * CE + ei;
            int base = w * (3 * EMB);
            g_w2[idx] = conv_w[(base + e) * KN + n]
                      + cvs[e] * conv_w[(base + EMB + e) * KN + n]
                      -          conv_w[(base + 2 * EMB + e) * KN + n];
        }
    }
}

// ---------------- main fused kernel: one document per CTA ----------------
// smem floats: E 100*308 | Ws 15000 | convs 96*50 | enc 152 | mlp1 76 | docids 100
#define SMEM_FLOATS (SEQ * EPAD + CHFLT + LP * KN + 152 + 76 + 100)

__global__ __launch_bounds__(256, 1)
void dazer_main(const int* __restrict__ input_d,
                const float* __restrict__ emb,
                const float* __restrict__ hid_w,
                const float* __restrict__ hid_b,
                const float* __restrict__ score_w,
                const float* __restrict__ score_b,
                float* __restrict__ out, int Btot) {
    extern __shared__ float sm[];
    float* E      = sm;                         // [100][308]
    float* Ws     = E + SEQ * EPAD;             // [50][5][60] chunk  (16B aligned)
    float* convs  = Ws + CHFLT;                 // [96][50]
    float* enc    = convs + LP * KN;            // [152]
    float* mlp1s  = enc + 152;                  // [76]
    int*   docids = (int*)(mlp1s + 76);         // [100]

    const int tid = threadIdx.x;
    const int b   = blockIdx.x;

    if (tid < SEQ) docids[tid] = input_d[b * SEQ + tid];
    __syncthreads();

    // gather embeddings (coalesced LDG -> padded smem rows)
    for (int idx = tid; idx < SEQ * EMB; idx += 256) {
        int s = idx / EMB;
        int e = idx - s * EMB;
        E[s * EPAD + e] = emb[(size_t)docids[s] * EMB + e];
    }

    // thread tile: 4 t-rows x 5 filters. 240 real tiles; threads 240..255
    // recompute tile (23,9) as dummies so ALL threads hit barriers.
    int tg = tid / 10;          // 0..25
    int ng = tid - tg * 10;     // 0..9
    const bool real = (tid < 240);
    if (!real) { tg = 23; ng = 9; }
    const int t0 = tg * 4;
    const int n0 = ng * 5;

    float2 acc[4][5];
    #pragma unroll
    for (int k = 0; k < 4; k++)
        #pragma unroll
        for (int j = 0; j < 5; j++) acc[k][j] = make_float2(0.f, 0.f);

    const float4* __restrict__ Wsrc = (const float4*)g_w2;
    float4* Ws4 = (float4*)Ws;

    #pragma unroll 1
    for (int c = 0; c < NCH; c++) {
        __syncthreads();   // previous chunk fully consumed (also covers E-gather on c==0)
        // stage 60KB W chunk (perfectly coalesced float4 copy)
        {
            const float4* src = Wsrc + c * (CHFLT / 4);
            #pragma unroll
            for (int i = 0; i < CHFLT / 4 / 256 + 1; i++) {
                int idx = i * 256 + tid;
                if (idx < CHFLT / 4) Ws4[idx] = src[idx];
            }
        }
        __syncthreads();

        #pragma unroll 1
        for (int eql = 0; eql < CQ; eql++) {
            const int ecol = c * CE + eql * 4;
            // E rows t0..t0+7, this e-quad (LDS.128, warp-broadcast across tg groups)
            float4 E4[8];
            #pragma unroll
            for (int k = 0; k < 8; k++)
                E4[k] = *(const float4*)&E[(t0 + k) * EPAD + ecol];

            #pragma unroll
            for (int j = 0; j < 5; j++) {
                #pragma unroll
                for (int w = 0; w < 5; w++) {
                    // LDS.128 broadcast: 10 threads share each address
                    float4 w4 = Ws4[((n0 + j) * KW + w) * CQ + eql];
                    float2 wlo = make_float2(w4.x, w4.y);
                    float2 whi = make_float2(w4.z, w4.w);
                    #pragma unroll
                    for (int k = 0; k < 4; k++) {
                        float2 elo = make_float2(E4[w + k].x, E4[w + k].y);
                        float2 ehi = make_float2(E4[w + k].z, E4[w + k].w);
                        acc[k][j] = ffma2(elo, wlo, acc[k][j]);
                        acc[k][j] = ffma2(ehi, whi, acc[k][j]);
                    }
                }
            }
        }
    }

    // gate + bias, write conv outputs to smem
    if (real) {
        #pragma unroll
        for (int j = 0; j < 5; j++) {
            int n = n0 + j;
            float gg = g_gate[n], bb = g_bias[n];
            #pragma unroll
            for (int k = 0; k < 4; k++)
                convs[(t0 + k) * KN + n] = gg * ((acc[k][j].x + acc[k][j].y) + bb);
        }
    }
    __syncthreads();

    // top-3 (kmax) per filter, original-order (strict > == jax top_k tie-break)
    if (tid < KN) {
        const int n = tid;
        float v1 = -1e30f, v2 = -1e30f, v3 = -1e30f;
        int   i1 = 0, i2 = 0, i3 = 0;
        for (int t = 0; t < LP; t++) {
            float v = convs[t * KN + n];
            if (v > v1)      { v3 = v2; i3 = i2; v2 = v1; i2 = i1; v1 = v; i1 = t; }
            else if (v > v2) { v3 = v2; i3 = i2; v2 = v;  i2 = t; }
            else if (v > v3) { v3 = v;  i3 = t; }
        }
        float va = v1, vb = v2, vc = v3; int ia = i1, ib = i2, ic = i3;
        if (ia > ib) { float tv = va; va = vb; vb = tv; int ti = ia; ia = ib; ib = ti; }
        if (ib > ic) { float tv = vb; vb = vc; vc = tv; int ti = ib; ib = ic; ic = ti; }
        if (ia > ib) { float tv = va; va = vb; vb = tv; int ti = ia; ia = ib; ib = ti; }
        enc[n * 3 + 0] = va;
        enc[n * 3 + 1] = vb;
        enc[n * 3 + 2] = vc;
    }
    __syncthreads();

    // mlp1 = tanh(enc @ hid_w + hid_b)
    if (tid < MLP1) {
        float s = hid_b[tid];
        #pragma unroll 5
        for (int i = 0; i < KN * KMAX; i++) s += enc[i] * hid_w[i * MLP1 + tid];
        float m = tanhf(s);
        mlp1s[tid] = m;
        out[(size_t)b * MLP1 + tid] = m;
    }
    __syncthreads();

    // score = tanh(mlp1 @ score_w + score_b)
    if (tid == 0) {
        float s = score_b[0];
        for (int j = 0; j < MLP1; j++) s += mlp1s[j] * score_w[j];
        out[(size_t)Btot * MLP1 + b] = tanhf(s);
    }
}

// ---------------- launch ----------------
extern "C" void kernel_launch(void* const* d_in, const int* in_sizes, int n_in,
                              void* d_out, int out_size) {
    const int*   input_q   = (const int*)  d_in[0];
    const int*   input_d   = (const int*)  d_in[1];
    const float* emb_table = (const float*)d_in[2];
    const float* conv_w    = (const float*)d_in[3];
    const float* conv_b    = (const float*)d_in[4];
    const float* gate_w    = (const float*)d_in[5];
    const float* gate_b    = (const float*)d_in[6];
    const float* hid_w     = (const float*)d_in[7];
    const float* hid_b     = (const float*)d_in[8];
    const float* score_w   = (const float*)d_in[9];
    const float* score_b   = (const float*)d_in[10];
    float* out = (float*)d_out;

    const int Btot = in_sizes[1] / SEQ;   // 2048
    const int smem_bytes = SMEM_FLOATS * (int)sizeof(float);

    cudaFuncSetAttribute(dazer_main, cudaFuncAttributeMaxDynamicSharedMemorySize, smem_bytes);

    dazer_prepA<<<1, 320>>>(input_q, emb_table);
    dazer_prepB<<<150, 256>>>(conv_w, conv_b, gate_w, gate_b);
    dazer_main<<<Btot, 256, smem_bytes>>>(input_d, emb_table, hid_w, hid_b,
                                          score_w, score_b, out, Btot);
}